// round 3
// baseline (speedup 1.0000x reference)
#include <cuda_runtime.h>
#include <math.h>

// Problem dims (fixed by reference)
#define BB   4
#define SS   2048
#define DD   1024
#define HH   16
#define DK   64
#define DFF  4096
#define NROW (BB*SS)          // 8192
#define LEPS 1e-6f

// ---------------- scratch (static __device__, no allocations) ----------------
__device__ float g_xn  [(size_t)NROW * DD];
__device__ float g_q   [(size_t)NROW * DD];
__device__ float g_k   [(size_t)NROW * DD];
__device__ float g_v   [(size_t)NROW * DD];
__device__ float g_attn[(size_t)NROW * DD];
__device__ float g_x1  [(size_t)NROW * DD];
__device__ float g_h   [(size_t)NROW * DFF];

// ---------------- LayerNorm (ddof=1, divide by std+eps) ----------------------
__global__ void ln_kernel(const float* __restrict__ x,
                          const float* __restrict__ w,
                          const float* __restrict__ b,
                          float* __restrict__ y)
{
    int row = blockIdx.x;
    const float* xr = x + (size_t)row * DD;
    int c = threadIdx.x * 4;                       // 256 threads * 4 = 1024
    float4 v = *(const float4*)(xr + c);
    float s  = v.x + v.y + v.z + v.w;
    float sq = v.x*v.x + v.y*v.y + v.z*v.z + v.w*v.w;
    #pragma unroll
    for (int o = 16; o; o >>= 1) {
        s  += __shfl_xor_sync(0xffffffffu, s,  o);
        sq += __shfl_xor_sync(0xffffffffu, sq, o);
    }
    __shared__ float ssm[8], sqm[8];
    int wid = threadIdx.x >> 5, lid = threadIdx.x & 31;
    if (lid == 0) { ssm[wid] = s; sqm[wid] = sq; }
    __syncthreads();
    if (wid == 0) {
        float a = (lid < 8) ? ssm[lid] : 0.f;
        float q = (lid < 8) ? sqm[lid] : 0.f;
        #pragma unroll
        for (int o = 16; o; o >>= 1) {
            a += __shfl_xor_sync(0xffffffffu, a, o);
            q += __shfl_xor_sync(0xffffffffu, q, o);
        }
        if (lid == 0) { ssm[0] = a; sqm[0] = q; }
    }
    __syncthreads();
    float sum = ssm[0], sumsq = sqm[0];
    float mean = sum * (1.0f / DD);
    float var  = (sumsq - sum * mean) * (1.0f / (DD - 1));
    float inv  = 1.0f / (sqrtf(var) + LEPS);

    float4 wv = *(const float4*)(w + c);
    float4 bv = *(const float4*)(b + c);
    float4 out;
    out.x = wv.x * (v.x - mean) * inv + bv.x;
    out.y = wv.y * (v.y - mean) * inv + bv.y;
    out.z = wv.z * (v.z - mean) * inv + bv.z;
    out.w = wv.w * (v.w - mean) * inv + bv.w;
    *(float4*)(y + (size_t)row * DD + c) = out;
}

// ---------------- SGEMM core (device inline) ---------------------------------
// 128x128 tile, BK=8, 256 threads, 8x8 per-thread microtile, double-buffered.
// MODE: 0 = bias, 1 = bias+relu, 2 = bias+residual
template<int MODE>
__device__ __forceinline__
void sgemm_body(const float* __restrict__ A, const float* __restrict__ W,
                const float* __restrict__ bias, const float* __restrict__ resid,
                float* __restrict__ C, int K, int M, int bx, int by)
{
    __shared__ float As[2][8][128];
    __shared__ float Ws[2][8][128];

    int tid = threadIdx.x;
    int tx = tid & 15, ty = tid >> 4;
    int row0 = by * 128;
    int col0 = bx * 128;

    int ar = tid >> 1, ak = (tid & 1) * 4;     // A: 128 rows x 8 k
    int wk = tid >> 5, wc = (tid & 31) * 4;    // W: 8 k x 128 cols

    const float* Aptr = A + (size_t)(row0 + ar) * K + ak;
    const float* Wptr = W + (size_t)wk * M + col0 + wc;

    float acc[8][8];
    #pragma unroll
    for (int i = 0; i < 8; i++)
        #pragma unroll
        for (int j = 0; j < 8; j++) acc[i][j] = 0.f;

    // prologue: tile 0 -> buf 0
    {
        float4 av = *(const float4*)(Aptr);
        float4 wv = *(const float4*)(Wptr);
        As[0][ak + 0][ar] = av.x; As[0][ak + 1][ar] = av.y;
        As[0][ak + 2][ar] = av.z; As[0][ak + 3][ar] = av.w;
        *(float4*)&Ws[0][wk][wc] = wv;
    }
    __syncthreads();

    int buf = 0;
    for (int k0 = 0; k0 < K; k0 += 8) {
        float4 av2, wv2;
        const bool more = (k0 + 8) < K;
        if (more) {
            av2 = *(const float4*)(Aptr + k0 + 8);
            wv2 = *(const float4*)(Wptr + (size_t)(k0 + 8) * M);
        }
        #pragma unroll
        for (int kk = 0; kk < 8; kk++) {
            float a[8], w8[8];
            *(float4*)&a[0]  = *(const float4*)&As[buf][kk][ty * 8];
            *(float4*)&a[4]  = *(const float4*)&As[buf][kk][ty * 8 + 4];
            *(float4*)&w8[0] = *(const float4*)&Ws[buf][kk][tx * 8];
            *(float4*)&w8[4] = *(const float4*)&Ws[buf][kk][tx * 8 + 4];
            #pragma unroll
            for (int i = 0; i < 8; i++)
                #pragma unroll
                for (int j = 0; j < 8; j++)
                    acc[i][j] = fmaf(a[i], w8[j], acc[i][j]);
        }
        if (more) {
            int nb = buf ^ 1;
            As[nb][ak + 0][ar] = av2.x; As[nb][ak + 1][ar] = av2.y;
            As[nb][ak + 2][ar] = av2.z; As[nb][ak + 3][ar] = av2.w;
            *(float4*)&Ws[nb][wk][wc] = wv2;
            __syncthreads();
            buf = nb;
        }
    }

    float b8[8];
    *(float4*)&b8[0] = *(const float4*)&bias[col0 + tx * 8];
    *(float4*)&b8[4] = *(const float4*)&bias[col0 + tx * 8 + 4];

    #pragma unroll
    for (int i = 0; i < 8; i++) {
        size_t base = (size_t)(row0 + ty * 8 + i) * M + col0 + tx * 8;
        float out[8];
        #pragma unroll
        for (int j = 0; j < 8; j++) {
            float v = acc[i][j] + b8[j];
            if (MODE == 1) v = fmaxf(v, 0.f);
            out[j] = v;
        }
        if (MODE == 2) {
            float r8[8];
            *(float4*)&r8[0] = *(const float4*)(resid + base);
            *(float4*)&r8[4] = *(const float4*)(resid + base + 4);
            #pragma unroll
            for (int j = 0; j < 8; j++) out[j] += r8[j];
        }
        *(float4*)(C + base)     = *(float4*)&out[0];
        *(float4*)(C + base + 4) = *(float4*)&out[4];
    }
}

template<int MODE>
__global__ __launch_bounds__(256, 2)
void sgemm_kernel(const float* __restrict__ A, const float* __restrict__ W,
                  const float* __restrict__ bias, const float* __restrict__ resid,
                  float* __restrict__ C, int K, int M)
{
    sgemm_body<MODE>(A, W, bias, resid, C, K, M, blockIdx.x, blockIdx.y);
}

// Fused QKV: blockIdx.z in {0,1,2} selects (W, bias, C) triple. One launch,
// one big wave set (1536 CTAs), shared A operand reused through L2.
__global__ __launch_bounds__(256, 2)
void qkv_kernel(const float* __restrict__ A,
                const float* __restrict__ wq, const float* __restrict__ bq,
                const float* __restrict__ wk, const float* __restrict__ bk,
                const float* __restrict__ wv, const float* __restrict__ bv,
                float* __restrict__ q, float* __restrict__ k, float* __restrict__ v)
{
    const float* W; const float* bias; float* C;
    if (blockIdx.z == 0)      { W = wq; bias = bq; C = q; }
    else if (blockIdx.z == 1) { W = wk; bias = bk; C = k; }
    else                      { W = wv; bias = bv; C = v; }
    sgemm_body<0>(A, W, bias, nullptr, C, DD, DD, blockIdx.x, blockIdx.y);
}

// ---------------- Flash attention (fp32, Br=Bc=64, dk=64) --------------------
// grid: (S/64, H, B), block: 256 (16x16), each thread 4x4 of S and O tiles.
#define FLASH_SMEM_FLOATS (4096*3 + 64*68)
__global__ __launch_bounds__(256)
void flash_kernel(const float* __restrict__ Q, const float* __restrict__ Kk,
                  const float* __restrict__ V, const int* __restrict__ mask,
                  float* __restrict__ O)
{
    extern __shared__ float sm[];
    float* Qs = sm;            // transposed: Qs[d*64 + q]
    float* Ks = sm + 4096;     // transposed: Ks[d*64 + k]
    float* Vs = sm + 8192;     // natural:    Vs[k*64 + d]
    float* Ps = sm + 12288;    // Ps[q*68 + k] (padded stride)
    __shared__ int ms[64];

    int tid = threadIdx.x;
    int tx = tid & 15, ty = tid >> 4;
    int q0 = blockIdx.x * 64;
    int h  = blockIdx.y;
    int b  = blockIdx.z;

    const float* Qb = Q  + ((size_t)(b * SS + q0)) * DD + h * DK;
    const float* Kb = Kk + ((size_t)b * SS) * DD + h * DK;
    const float* Vb = V  + ((size_t)b * SS) * DD + h * DK;
    const int*   mb = mask + b * SS;

    // Load Q tile (transposed into smem)
    #pragma unroll
    for (int it = tid; it < 1024; it += 256) {
        int qq = it >> 4; int d0 = (it & 15) << 2;
        float4 v = *(const float4*)(Qb + (size_t)qq * DD + d0);
        Qs[(d0 + 0) * 64 + qq] = v.x; Qs[(d0 + 1) * 64 + qq] = v.y;
        Qs[(d0 + 2) * 64 + qq] = v.z; Qs[(d0 + 3) * 64 + qq] = v.w;
    }

    float m[4], l[4], o[4][4];
    #pragma unroll
    for (int i = 0; i < 4; i++) {
        m[i] = -INFINITY; l[i] = 0.f;
        #pragma unroll
        for (int j = 0; j < 4; j++) o[i][j] = 0.f;
    }

    for (int kt = 0; kt < SS / 64; kt++) {
        int k0 = kt * 64;
        __syncthreads();   // prior GEMM2 reads done (covers Q load on iter 0)
        #pragma unroll
        for (int it = tid; it < 1024; it += 256) {
            int r = it >> 4; int d0 = (it & 15) << 2;
            float4 kv = *(const float4*)(Kb + (size_t)(k0 + r) * DD + d0);
            Ks[(d0 + 0) * 64 + r] = kv.x; Ks[(d0 + 1) * 64 + r] = kv.y;
            Ks[(d0 + 2) * 64 + r] = kv.z; Ks[(d0 + 3) * 64 + r] = kv.w;
            float4 vv = *(const float4*)(Vb + (size_t)(k0 + r) * DD + d0);
            *(float4*)&Vs[r * 64 + d0] = vv;
        }
        if (tid < 64) ms[tid] = mb[k0 + tid];
        __syncthreads();

        // S = Q @ K^T
        float s[4][4];
        #pragma unroll
        for (int i = 0; i < 4; i++)
            #pragma unroll
            for (int j = 0; j < 4; j++) s[i][j] = 0.f;
        #pragma unroll 8
        for (int d = 0; d < 64; d++) {
            float a[4], bq[4];
            *(float4*)a  = *(const float4*)&Qs[d * 64 + ty * 4];
            *(float4*)bq = *(const float4*)&Ks[d * 64 + tx * 4];
            #pragma unroll
            for (int i = 0; i < 4; i++)
                #pragma unroll
                for (int j = 0; j < 4; j++)
                    s[i][j] = fmaf(a[i], bq[j], s[i][j]);
        }
        #pragma unroll
        for (int i = 0; i < 4; i++)
            #pragma unroll
            for (int j = 0; j < 4; j++) {
                s[i][j] *= 0.125f;                    // 1/sqrt(64)
                if (ms[tx * 4 + j] == 0) s[i][j] = -INFINITY;
            }

        // online softmax per row (rows owned: ty*4 + i; reduce across 16 tx lanes)
        #pragma unroll
        for (int i = 0; i < 4; i++) {
            float mx = fmaxf(fmaxf(s[i][0], s[i][1]), fmaxf(s[i][2], s[i][3]));
            #pragma unroll
            for (int off = 8; off; off >>= 1)
                mx = fmaxf(mx, __shfl_xor_sync(0xffffffffu, mx, off));
            float mn = fmaxf(m[i], mx);
            float sc = (m[i] == -INFINITY) ? 0.f : __expf(m[i] - mn);
            float sum = 0.f;
            #pragma unroll
            for (int j = 0; j < 4; j++) {
                float p = __expf(s[i][j] - mn);
                s[i][j] = p; sum += p;
            }
            #pragma unroll
            for (int off = 8; off; off >>= 1)
                sum += __shfl_xor_sync(0xffffffffu, sum, off);
            l[i] = l[i] * sc + sum;
            m[i] = mn;
            #pragma unroll
            for (int j = 0; j < 4; j++) o[i][j] *= sc;
        }

        // stash P
        #pragma unroll
        for (int i = 0; i < 4; i++)
            #pragma unroll
            for (int j = 0; j < 4; j++)
                Ps[(ty * 4 + i) * 68 + tx * 4 + j] = s[i][j];
        __syncthreads();

        // O += P @ V
        #pragma unroll 8
        for (int k = 0; k < 64; k++) {
            float a0 = Ps[(ty * 4 + 0) * 68 + k];
            float a1 = Ps[(ty * 4 + 1) * 68 + k];
            float a2 = Ps[(ty * 4 + 2) * 68 + k];
            float a3 = Ps[(ty * 4 + 3) * 68 + k];
            float4 bv = *(const float4*)&Vs[k * 64 + tx * 4];
            o[0][0] = fmaf(a0, bv.x, o[0][0]); o[0][1] = fmaf(a0, bv.y, o[0][1]);
            o[0][2] = fmaf(a0, bv.z, o[0][2]); o[0][3] = fmaf(a0, bv.w, o[0][3]);
            o[1][0] = fmaf(a1, bv.x, o[1][0]); o[1][1] = fmaf(a1, bv.y, o[1][1]);
            o[1][2] = fmaf(a1, bv.z, o[1][2]); o[1][3] = fmaf(a1, bv.w, o[1][3]);
            o[2][0] = fmaf(a2, bv.x, o[2][0]); o[2][1] = fmaf(a2, bv.y, o[2][1]);
            o[2][2] = fmaf(a2, bv.z, o[2][2]); o[2][3] = fmaf(a2, bv.w, o[2][3]);
            o[3][0] = fmaf(a3, bv.x, o[3][0]); o[3][1] = fmaf(a3, bv.y, o[3][1]);
            o[3][2] = fmaf(a3, bv.z, o[3][2]); o[3][3] = fmaf(a3, bv.w, o[3][3]);
        }
    }

    float* Ob = O + ((size_t)(b * SS + q0)) * DD + h * DK;
    #pragma unroll
    for (int i = 0; i < 4; i++) {
        float invl = 1.0f / l[i];
        float4 out;
        out.x = o[i][0] * invl; out.y = o[i][1] * invl;
        out.z = o[i][2] * invl; out.w = o[i][3] * invl;
        *(float4*)(Ob + (size_t)(ty * 4 + i) * DD + tx * 4) = out;
    }
}

// ---------------- launch ------------------------------------------------------
extern "C" void kernel_launch(void* const* d_in, const int* in_sizes, int n_in,
                              void* d_out, int out_size)
{
    const float* x    = (const float*)d_in[0];
    const int*   mask = (const int*)  d_in[1];
    const float* wq   = (const float*)d_in[2];
    const float* bq   = (const float*)d_in[3];
    const float* wk   = (const float*)d_in[4];
    const float* bk   = (const float*)d_in[5];
    const float* wv   = (const float*)d_in[6];
    const float* bv   = (const float*)d_in[7];
    const float* wo   = (const float*)d_in[8];
    const float* bo   = (const float*)d_in[9];
    const float* w1   = (const float*)d_in[10];
    const float* b1   = (const float*)d_in[11];
    const float* w2   = (const float*)d_in[12];
    const float* b2   = (const float*)d_in[13];
    const float* ln1w = (const float*)d_in[14];
    const float* ln1b = (const float*)d_in[15];
    const float* ln2w = (const float*)d_in[16];
    const float* ln2b = (const float*)d_in[17];
    float* out = (float*)d_out;

    float *xn, *q, *k, *v, *attn, *x1, *hb;
    cudaGetSymbolAddress((void**)&xn,   g_xn);
    cudaGetSymbolAddress((void**)&q,    g_q);
    cudaGetSymbolAddress((void**)&k,    g_k);
    cudaGetSymbolAddress((void**)&v,    g_v);
    cudaGetSymbolAddress((void**)&attn, g_attn);
    cudaGetSymbolAddress((void**)&x1,   g_x1);
    cudaGetSymbolAddress((void**)&hb,   g_h);

    cudaFuncSetAttribute(flash_kernel,
                         cudaFuncAttributeMaxDynamicSharedMemorySize,
                         FLASH_SMEM_FLOATS * (int)sizeof(float));

    dim3 gD  (DD  / 128, NROW / 128);      // M=1024 GEMMs
    dim3 gQKV(DD  / 128, NROW / 128, 3);   // fused QKV
    dim3 gF  (DFF / 128, NROW / 128);      // M=4096 GEMM
    dim3 gAtt(SS / 64, HH, BB);

    // 1) ln1
    ln_kernel<<<NROW, 256>>>(x, ln1w, ln1b, xn);
    // 2) fused Q, K, V projections
    qkv_kernel<<<gQKV, 256>>>(xn, wq, bq, wk, bk, wv, bv, q, k, v);
    // 3) attention
    flash_kernel<<<gAtt, 256, FLASH_SMEM_FLOATS * sizeof(float)>>>(q, k, v, mask, attn);
    // 4) output projection + residual
    sgemm_kernel<2><<<gD, 256>>>(attn, wo, bo, x, x1, DD, DD);
    // 5) ln2
    ln_kernel<<<NROW, 256>>>(x1, ln2w, ln2b, xn);
    // 6) FFN up + relu
    sgemm_kernel<1><<<gF, 256>>>(xn, w1, b1, nullptr, hb, DD, DFF);
    // 7) FFN down + residual -> out
    sgemm_kernel<2><<<gD, 256>>>(hb, w2, b2, x1, out, DFF, DD);
}

// round 4
// speedup vs baseline: 1.5613x; 1.5613x over previous
#include <cuda_runtime.h>
#include <math.h>
#include <stdint.h>

// Problem dims (fixed by reference)
#define BB   4
#define SS   2048
#define DD   1024
#define HH   16
#define DK   64
#define DFF  4096
#define NROW (BB*SS)          // 8192
#define LEPS 1e-6f

// ---------------- scratch (static __device__, no allocations) ----------------
__device__ float g_xn  [(size_t)NROW * DD];
__device__ float g_q   [(size_t)NROW * DD];
__device__ float g_k   [(size_t)NROW * DD];
__device__ float g_v   [(size_t)NROW * DD];
__device__ float g_attn[(size_t)NROW * DD];
__device__ float g_x1  [(size_t)NROW * DD];
__device__ float g_h   [(size_t)NROW * DFF];

// ---------------- LayerNorm (ddof=1, divide by std+eps) ----------------------
__global__ void ln_kernel(const float* __restrict__ x,
                          const float* __restrict__ w,
                          const float* __restrict__ b,
                          float* __restrict__ y)
{
    int row = blockIdx.x;
    const float* xr = x + (size_t)row * DD;
    int c = threadIdx.x * 4;                       // 256 threads * 4 = 1024
    float4 v = *(const float4*)(xr + c);
    float s  = v.x + v.y + v.z + v.w;
    float sq = v.x*v.x + v.y*v.y + v.z*v.z + v.w*v.w;
    #pragma unroll
    for (int o = 16; o; o >>= 1) {
        s  += __shfl_xor_sync(0xffffffffu, s,  o);
        sq += __shfl_xor_sync(0xffffffffu, sq, o);
    }
    __shared__ float ssm[8], sqm[8];
    int wid = threadIdx.x >> 5, lid = threadIdx.x & 31;
    if (lid == 0) { ssm[wid] = s; sqm[wid] = sq; }
    __syncthreads();
    if (wid == 0) {
        float a = (lid < 8) ? ssm[lid] : 0.f;
        float q = (lid < 8) ? sqm[lid] : 0.f;
        #pragma unroll
        for (int o = 16; o; o >>= 1) {
            a += __shfl_xor_sync(0xffffffffu, a, o);
            q += __shfl_xor_sync(0xffffffffu, q, o);
        }
        if (lid == 0) { ssm[0] = a; sqm[0] = q; }
    }
    __syncthreads();
    float sum = ssm[0], sumsq = sqm[0];
    float mean = sum * (1.0f / DD);
    float var  = (sumsq - sum * mean) * (1.0f / (DD - 1));
    float inv  = 1.0f / (sqrtf(var) + LEPS);

    float4 wv = *(const float4*)(w + c);
    float4 bv = *(const float4*)(b + c);
    float4 out;
    out.x = wv.x * (v.x - mean) * inv + bv.x;
    out.y = wv.y * (v.y - mean) * inv + bv.y;
    out.z = wv.z * (v.z - mean) * inv + bv.z;
    out.w = wv.w * (v.w - mean) * inv + bv.w;
    *(float4*)(y + (size_t)row * DD + c) = out;
}

// ---------------- TF32 tensor-core GEMM --------------------------------------
// C[N,M] = A[N,K] @ W[K,M] + bias (+relu / +resid)
// 128x128 tile, BK=16, 256 threads = 8 warps (2x4), warp tile 64x32.
// mma.sync.m16n8k8 tf32, fp32 accumulate, double-buffered smem.
// MODE: 0 = bias, 1 = bias+relu, 2 = bias+residual

__device__ __forceinline__ uint32_t f2tf(float f) {
    uint32_t u;
    asm("cvt.rna.tf32.f32 %0, %1;" : "=r"(u) : "f"(f));
    return u;
}

#define MMA_TF32(d, a, b)                                                     \
    asm volatile("mma.sync.aligned.m16n8k8.row.col.f32.tf32.tf32.f32 "        \
                 "{%0,%1,%2,%3},{%4,%5,%6,%7},{%8,%9},{%0,%1,%2,%3};"         \
                 : "+f"(d[0]), "+f"(d[1]), "+f"(d[2]), "+f"(d[3])             \
                 : "r"(a[0]), "r"(a[1]), "r"(a[2]), "r"(a[3]),                \
                   "r"(b[0]), "r"(b[1]))

template<int MODE>
__device__ __forceinline__
void tgemm_body(const float* __restrict__ A, const float* __restrict__ W,
                const float* __restrict__ bias, const float* __restrict__ resid,
                float* __restrict__ C, int K, int M, int bx, int by)
{
    __shared__ uint32_t As[2][16][132];   // [k][m], tf32 bits
    __shared__ uint32_t Ws[2][16][132];   // [k][n], tf32 bits

    int tid  = threadIdx.x;
    int lane = tid & 31, warp = tid >> 5;
    int wm = warp >> 2, wn = warp & 3;            // warp grid 2 x 4
    int g = lane >> 2, t = lane & 3;              // quad group / in-group id
    int row0 = by * 128, col0 = bx * 128;

    // staging assignments
    int ar = tid >> 1, ak = (tid & 1) * 8;        // A: 128 rows x 16 k, 8 k/thread
    int wk = tid >> 5, wc = (tid & 31) * 4;       // W: rows wk & wk+8, 4 cols

    const float* Aptr  = A + (size_t)(row0 + ar) * K + ak;
    const float* Wptr0 = W + (size_t)wk * M + col0 + wc;
    const float* Wptr1 = W + (size_t)(wk + 8) * M + col0 + wc;

    float acc[4][4][4];
    #pragma unroll
    for (int i = 0; i < 4; i++)
        #pragma unroll
        for (int j = 0; j < 4; j++)
            #pragma unroll
            for (int r = 0; r < 4; r++) acc[i][j][r] = 0.f;

    // prologue: tile 0 -> buf 0
    {
        float4 a0 = *(const float4*)(Aptr);
        float4 a1 = *(const float4*)(Aptr + 4);
        float4 w0 = *(const float4*)(Wptr0);
        float4 w1 = *(const float4*)(Wptr1);
        As[0][ak+0][ar] = f2tf(a0.x); As[0][ak+1][ar] = f2tf(a0.y);
        As[0][ak+2][ar] = f2tf(a0.z); As[0][ak+3][ar] = f2tf(a0.w);
        As[0][ak+4][ar] = f2tf(a1.x); As[0][ak+5][ar] = f2tf(a1.y);
        As[0][ak+6][ar] = f2tf(a1.z); As[0][ak+7][ar] = f2tf(a1.w);
        Ws[0][wk  ][wc+0] = f2tf(w0.x); Ws[0][wk  ][wc+1] = f2tf(w0.y);
        Ws[0][wk  ][wc+2] = f2tf(w0.z); Ws[0][wk  ][wc+3] = f2tf(w0.w);
        Ws[0][wk+8][wc+0] = f2tf(w1.x); Ws[0][wk+8][wc+1] = f2tf(w1.y);
        Ws[0][wk+8][wc+2] = f2tf(w1.z); Ws[0][wk+8][wc+3] = f2tf(w1.w);
    }
    __syncthreads();

    int buf = 0;
    for (int k0 = 0; k0 < K; k0 += 16) {
        float4 a0n, a1n, w0n, w1n;
        const bool more = (k0 + 16) < K;
        if (more) {
            a0n = *(const float4*)(Aptr + k0 + 16);
            a1n = *(const float4*)(Aptr + k0 + 20);
            w0n = *(const float4*)(Wptr0 + (size_t)(k0 + 16) * M);
            w1n = *(const float4*)(Wptr1 + (size_t)(k0 + 16) * M);
        }

        #pragma unroll
        for (int ks = 0; ks < 2; ks++) {
            int kk = ks * 8;
            uint32_t afr[4][4], bfr[4][2];
            #pragma unroll
            for (int im = 0; im < 4; im++) {
                int mb = wm * 64 + im * 16;
                afr[im][0] = As[buf][kk + t    ][mb + g    ];
                afr[im][1] = As[buf][kk + t    ][mb + g + 8];
                afr[im][2] = As[buf][kk + t + 4][mb + g    ];
                afr[im][3] = As[buf][kk + t + 4][mb + g + 8];
            }
            #pragma unroll
            for (int jn = 0; jn < 4; jn++) {
                int nb = wn * 32 + jn * 8;
                bfr[jn][0] = Ws[buf][kk + t    ][nb + g];
                bfr[jn][1] = Ws[buf][kk + t + 4][nb + g];
            }
            #pragma unroll
            for (int im = 0; im < 4; im++)
                #pragma unroll
                for (int jn = 0; jn < 4; jn++)
                    MMA_TF32(acc[im][jn], afr[im], bfr[jn]);
        }

        if (more) {
            int nb = buf ^ 1;
            As[nb][ak+0][ar] = f2tf(a0n.x); As[nb][ak+1][ar] = f2tf(a0n.y);
            As[nb][ak+2][ar] = f2tf(a0n.z); As[nb][ak+3][ar] = f2tf(a0n.w);
            As[nb][ak+4][ar] = f2tf(a1n.x); As[nb][ak+5][ar] = f2tf(a1n.y);
            As[nb][ak+6][ar] = f2tf(a1n.z); As[nb][ak+7][ar] = f2tf(a1n.w);
            Ws[nb][wk  ][wc+0] = f2tf(w0n.x); Ws[nb][wk  ][wc+1] = f2tf(w0n.y);
            Ws[nb][wk  ][wc+2] = f2tf(w0n.z); Ws[nb][wk  ][wc+3] = f2tf(w0n.w);
            Ws[nb][wk+8][wc+0] = f2tf(w1n.x); Ws[nb][wk+8][wc+1] = f2tf(w1n.y);
            Ws[nb][wk+8][wc+2] = f2tf(w1n.z); Ws[nb][wk+8][wc+3] = f2tf(w1n.w);
            __syncthreads();
            buf = nb;
        }
    }

    // epilogue
    #pragma unroll
    for (int im = 0; im < 4; im++) {
        int rA = row0 + wm * 64 + im * 16 + g;
        int rB = rA + 8;
        #pragma unroll
        for (int jn = 0; jn < 4; jn++) {
            int col = col0 + wn * 32 + jn * 8 + 2 * t;
            float bx0 = bias[col], bx1 = bias[col + 1];
            float v0 = acc[im][jn][0] + bx0;
            float v1 = acc[im][jn][1] + bx1;
            float v2 = acc[im][jn][2] + bx0;
            float v3 = acc[im][jn][3] + bx1;
            if (MODE == 1) {
                v0 = fmaxf(v0, 0.f); v1 = fmaxf(v1, 0.f);
                v2 = fmaxf(v2, 0.f); v3 = fmaxf(v3, 0.f);
            }
            size_t oA = (size_t)rA * M + col;
            size_t oB = (size_t)rB * M + col;
            if (MODE == 2) {
                float2 r0 = *(const float2*)(resid + oA);
                float2 r1 = *(const float2*)(resid + oB);
                v0 += r0.x; v1 += r0.y; v2 += r1.x; v3 += r1.y;
            }
            float2 s0 = make_float2(v0, v1);
            float2 s1 = make_float2(v2, v3);
            *(float2*)(C + oA) = s0;
            *(float2*)(C + oB) = s1;
        }
    }
}

template<int MODE>
__global__ __launch_bounds__(256, 2)
void tgemm_kernel(const float* __restrict__ A, const float* __restrict__ W,
                  const float* __restrict__ bias, const float* __restrict__ resid,
                  float* __restrict__ C, int K, int M)
{
    tgemm_body<MODE>(A, W, bias, resid, C, K, M, blockIdx.x, blockIdx.y);
}

// Fused QKV: blockIdx.z selects (W, bias, C) triple.
__global__ __launch_bounds__(256, 2)
void qkv_kernel(const float* __restrict__ A,
                const float* __restrict__ wq, const float* __restrict__ bq,
                const float* __restrict__ wk, const float* __restrict__ bk,
                const float* __restrict__ wv, const float* __restrict__ bv,
                float* __restrict__ q, float* __restrict__ k, float* __restrict__ v)
{
    const float* W; const float* bias; float* C;
    if (blockIdx.z == 0)      { W = wq; bias = bq; C = q; }
    else if (blockIdx.z == 1) { W = wk; bias = bk; C = k; }
    else                      { W = wv; bias = bv; C = v; }
    tgemm_body<0>(A, W, bias, nullptr, C, DD, DD, blockIdx.x, blockIdx.y);
}

// ---------------- Flash attention (fp32, Br=Bc=64, dk=64) --------------------
#define FLASH_SMEM_FLOATS (4096*3 + 64*68)
__global__ __launch_bounds__(256)
void flash_kernel(const float* __restrict__ Q, const float* __restrict__ Kk,
                  const float* __restrict__ V, const int* __restrict__ mask,
                  float* __restrict__ O)
{
    extern __shared__ float sm[];
    float* Qs = sm;            // transposed: Qs[d*64 + q]
    float* Ks = sm + 4096;     // transposed: Ks[d*64 + k]
    float* Vs = sm + 8192;     // natural:    Vs[k*64 + d]
    float* Ps = sm + 12288;    // Ps[q*68 + k] (padded stride)
    __shared__ int ms[64];

    int tid = threadIdx.x;
    int tx = tid & 15, ty = tid >> 4;
    int q0 = blockIdx.x * 64;
    int h  = blockIdx.y;
    int b  = blockIdx.z;

    const float* Qb = Q  + ((size_t)(b * SS + q0)) * DD + h * DK;
    const float* Kb = Kk + ((size_t)b * SS) * DD + h * DK;
    const float* Vb = V  + ((size_t)b * SS) * DD + h * DK;
    const int*   mb = mask + b * SS;

    #pragma unroll
    for (int it = tid; it < 1024; it += 256) {
        int qq = it >> 4; int d0 = (it & 15) << 2;
        float4 v = *(const float4*)(Qb + (size_t)qq * DD + d0);
        Qs[(d0 + 0) * 64 + qq] = v.x; Qs[(d0 + 1) * 64 + qq] = v.y;
        Qs[(d0 + 2) * 64 + qq] = v.z; Qs[(d0 + 3) * 64 + qq] = v.w;
    }

    float m[4], l[4], o[4][4];
    #pragma unroll
    for (int i = 0; i < 4; i++) {
        m[i] = -INFINITY; l[i] = 0.f;
        #pragma unroll
        for (int j = 0; j < 4; j++) o[i][j] = 0.f;
    }

    for (int kt = 0; kt < SS / 64; kt++) {
        int k0 = kt * 64;
        __syncthreads();
        #pragma unroll
        for (int it = tid; it < 1024; it += 256) {
            int r = it >> 4; int d0 = (it & 15) << 2;
            float4 kv = *(const float4*)(Kb + (size_t)(k0 + r) * DD + d0);
            Ks[(d0 + 0) * 64 + r] = kv.x; Ks[(d0 + 1) * 64 + r] = kv.y;
            Ks[(d0 + 2) * 64 + r] = kv.z; Ks[(d0 + 3) * 64 + r] = kv.w;
            float4 vv = *(const float4*)(Vb + (size_t)(k0 + r) * DD + d0);
            *(float4*)&Vs[r * 64 + d0] = vv;
        }
        if (tid < 64) ms[tid] = mb[k0 + tid];
        __syncthreads();

        float s[4][4];
        #pragma unroll
        for (int i = 0; i < 4; i++)
            #pragma unroll
            for (int j = 0; j < 4; j++) s[i][j] = 0.f;
        #pragma unroll 8
        for (int d = 0; d < 64; d++) {
            float a[4], bq[4];
            *(float4*)a  = *(const float4*)&Qs[d * 64 + ty * 4];
            *(float4*)bq = *(const float4*)&Ks[d * 64 + tx * 4];
            #pragma unroll
            for (int i = 0; i < 4; i++)
                #pragma unroll
                for (int j = 0; j < 4; j++)
                    s[i][j] = fmaf(a[i], bq[j], s[i][j]);
        }
        #pragma unroll
        for (int i = 0; i < 4; i++)
            #pragma unroll
            for (int j = 0; j < 4; j++) {
                s[i][j] *= 0.125f;
                if (ms[tx * 4 + j] == 0) s[i][j] = -INFINITY;
            }

        #pragma unroll
        for (int i = 0; i < 4; i++) {
            float mx = fmaxf(fmaxf(s[i][0], s[i][1]), fmaxf(s[i][2], s[i][3]));
            #pragma unroll
            for (int off = 8; off; off >>= 1)
                mx = fmaxf(mx, __shfl_xor_sync(0xffffffffu, mx, off));
            float mn = fmaxf(m[i], mx);
            float sc = (m[i] == -INFINITY) ? 0.f : __expf(m[i] - mn);
            float sum = 0.f;
            #pragma unroll
            for (int j = 0; j < 4; j++) {
                float p = __expf(s[i][j] - mn);
                s[i][j] = p; sum += p;
            }
            #pragma unroll
            for (int off = 8; off; off >>= 1)
                sum += __shfl_xor_sync(0xffffffffu, sum, off);
            l[i] = l[i] * sc + sum;
            m[i] = mn;
            #pragma unroll
            for (int j = 0; j < 4; j++) o[i][j] *= sc;
        }

        #pragma unroll
        for (int i = 0; i < 4; i++)
            #pragma unroll
            for (int j = 0; j < 4; j++)
                Ps[(ty * 4 + i) * 68 + tx * 4 + j] = s[i][j];
        __syncthreads();

        #pragma unroll 8
        for (int k = 0; k < 64; k++) {
            float a0 = Ps[(ty * 4 + 0) * 68 + k];
            float a1 = Ps[(ty * 4 + 1) * 68 + k];
            float a2 = Ps[(ty * 4 + 2) * 68 + k];
            float a3 = Ps[(ty * 4 + 3) * 68 + k];
            float4 bv = *(const float4*)&Vs[k * 64 + tx * 4];
            o[0][0] = fmaf(a0, bv.x, o[0][0]); o[0][1] = fmaf(a0, bv.y, o[0][1]);
            o[0][2] = fmaf(a0, bv.z, o[0][2]); o[0][3] = fmaf(a0, bv.w, o[0][3]);
            o[1][0] = fmaf(a1, bv.x, o[1][0]); o[1][1] = fmaf(a1, bv.y, o[1][1]);
            o[1][2] = fmaf(a1, bv.z, o[1][2]); o[1][3] = fmaf(a1, bv.w, o[1][3]);
            o[2][0] = fmaf(a2, bv.x, o[2][0]); o[2][1] = fmaf(a2, bv.y, o[2][1]);
            o[2][2] = fmaf(a2, bv.z, o[2][2]); o[2][3] = fmaf(a2, bv.w, o[2][3]);
            o[3][0] = fmaf(a3, bv.x, o[3][0]); o[3][1] = fmaf(a3, bv.y, o[3][1]);
            o[3][2] = fmaf(a3, bv.z, o[3][2]); o[3][3] = fmaf(a3, bv.w, o[3][3]);
        }
    }

    float* Ob = O + ((size_t)(b * SS + q0)) * DD + h * DK;
    #pragma unroll
    for (int i = 0; i < 4; i++) {
        float invl = 1.0f / l[i];
        float4 out;
        out.x = o[i][0] * invl; out.y = o[i][1] * invl;
        out.z = o[i][2] * invl; out.w = o[i][3] * invl;
        *(float4*)(Ob + (size_t)(ty * 4 + i) * DD + tx * 4) = out;
    }
}

// ---------------- launch ------------------------------------------------------
extern "C" void kernel_launch(void* const* d_in, const int* in_sizes, int n_in,
                              void* d_out, int out_size)
{
    const float* x    = (const float*)d_in[0];
    const int*   mask = (const int*)  d_in[1];
    const float* wq   = (const float*)d_in[2];
    const float* bq   = (const float*)d_in[3];
    const float* wk   = (const float*)d_in[4];
    const float* bk   = (const float*)d_in[5];
    const float* wv   = (const float*)d_in[6];
    const float* bv   = (const float*)d_in[7];
    const float* wo   = (const float*)d_in[8];
    const float* bo   = (const float*)d_in[9];
    const float* w1   = (const float*)d_in[10];
    const float* b1   = (const float*)d_in[11];
    const float* w2   = (const float*)d_in[12];
    const float* b2   = (const float*)d_in[13];
    const float* ln1w = (const float*)d_in[14];
    const float* ln1b = (const float*)d_in[15];
    const float* ln2w = (const float*)d_in[16];
    const float* ln2b = (const float*)d_in[17];
    float* out = (float*)d_out;

    float *xn, *q, *k, *v, *attn, *x1, *hb;
    cudaGetSymbolAddress((void**)&xn,   g_xn);
    cudaGetSymbolAddress((void**)&q,    g_q);
    cudaGetSymbolAddress((void**)&k,    g_k);
    cudaGetSymbolAddress((void**)&v,    g_v);
    cudaGetSymbolAddress((void**)&attn, g_attn);
    cudaGetSymbolAddress((void**)&x1,   g_x1);
    cudaGetSymbolAddress((void**)&hb,   g_h);

    cudaFuncSetAttribute(flash_kernel,
                         cudaFuncAttributeMaxDynamicSharedMemorySize,
                         FLASH_SMEM_FLOATS * (int)sizeof(float));

    dim3 gD  (DD  / 128, NROW / 128);      // M=1024 GEMMs
    dim3 gQKV(DD  / 128, NROW / 128, 3);   // fused QKV
    dim3 gF  (DFF / 128, NROW / 128);      // M=4096 GEMM
    dim3 gAtt(SS / 64, HH, BB);

    // 1) ln1
    ln_kernel<<<NROW, 256>>>(x, ln1w, ln1b, xn);
    // 2) fused Q, K, V projections (tf32 tensor cores)
    qkv_kernel<<<gQKV, 256>>>(xn, wq, bq, wk, bk, wv, bv, q, k, v);
    // 3) attention
    flash_kernel<<<gAtt, 256, FLASH_SMEM_FLOATS * sizeof(float)>>>(q, k, v, mask, attn);
    // 4) output projection + residual
    tgemm_kernel<2><<<gD, 256>>>(attn, wo, bo, x, x1, DD, DD);
    // 5) ln2
    ln_kernel<<<NROW, 256>>>(x1, ln2w, ln2b, xn);
    // 6) FFN up + relu
    tgemm_kernel<1><<<gF, 256>>>(xn, w1, b1, nullptr, hb, DD, DFF);
    // 7) FFN down + residual -> out
    tgemm_kernel<2><<<gD, 256>>>(hb, w2, b2, x1, out, DFF, DD);
}